// round 11
// baseline (speedup 1.0000x reference)
#include <cuda_runtime.h>
#include <cuda_bf16.h>

typedef unsigned long long u64;
typedef unsigned int u32;

#define NROWS  65536
#define KC     4096
#define DIM    64
#define ROWS_B 128
#define NTILES 64          // B tiles of 64 codes
#define NBLK   512
#define CTA    256
#define MARGIN 1.2e-4f
#define ZP     68          // zsm pitch (floats)

// dynamic smem layout (bytes)
#define OFF_Z   0                         // 128*68*4 = 34816
#define OFF_Z2  34816                     // 128 floats
#define OFF_A   35328                     // 16384 (bf16 z plane, SW128)
#define OFF_B(buf) (51712 + (buf)*8192)   // 64 codes * 128B per buf
#define OFF_W2(buf) (68096 + (buf)*256)
#define SMEM_BYTES 68608

#define SWZ(x) ((x) ^ (((x) >> 3) & 0x70))

__device__ __nv_bfloat16 g_whi[KC * DIM];
__device__ float g_w2[KC];
__device__ int   g_idx[NROWS];
__device__ float g_part[4096];

// ---------------------------------------------------------------------------
__device__ __forceinline__ u32 smem_u32(const void* p) {
    u32 a;
    asm("{ .reg .u64 t; cvta.to.shared.u64 t, %1; cvt.u32.u64 %0, t; }"
        : "=r"(a) : "l"(p));
    return a;
}
__device__ __forceinline__ void cp16(u32 dst, const void* src) {
    asm volatile("cp.async.cg.shared.global [%0], [%1], 16;"
                 :: "r"(dst), "l"(src));
}
#define CP_COMMIT() asm volatile("cp.async.commit_group;" ::: "memory")
#define CP_WAIT0()  asm volatile("cp.async.wait_group 0;" ::: "memory")

__device__ __forceinline__ void ldsm4(u32& r0, u32& r1, u32& r2, u32& r3, u32 a) {
    asm volatile("ldmatrix.sync.aligned.m8n8.x4.shared.b16 {%0,%1,%2,%3}, [%4];"
                 : "=r"(r0), "=r"(r1), "=r"(r2), "=r"(r3) : "r"(a));
}
#define MMA(d, a, b0, b1)                                                     \
    asm volatile("mma.sync.aligned.m16n8k16.row.col.f32.bf16.bf16.f32 "       \
        "{%0,%1,%2,%3},{%4,%5,%6,%7},{%8,%9},{%0,%1,%2,%3};"                  \
        : "+f"((d)[0]), "+f"((d)[1]), "+f"((d)[2]), "+f"((d)[3])              \
        : "r"((a)[0]), "r"((a)[1]), "r"((a)[2]), "r"((a)[3]), "r"(b0), "r"(b1))

// ---------------------------------------------------------------------------
// prep: exact w2 (sequential ascending, proven order) + bf16(-2w)
// ---------------------------------------------------------------------------
__global__ void prep_kernel(const float* __restrict__ W) {
    int k = blockIdx.x * 256 + threadIdx.x;      // grid 16 x 256
    float s = 0.0f;
    #pragma unroll 8
    for (int j = 0; j < DIM; j++) {
        float wv = W[k * DIM + j];
        s = __fmaf_rn(wv, wv, s);
        g_whi[k * DIM + j] = __float2bfloat16(-2.0f * wv);
    }
    g_w2[k] = s;
}

// ---------------------------------------------------------------------------
__device__ __forceinline__ u64 rescore(int k, const float* zr, float z2r,
                                       const float* __restrict__ W) {
    const float* wr = W + (size_t)k * DIM;
    float s = 0.0f;
    #pragma unroll 8
    for (int j = 0; j < DIM; j++) s = __fmaf_rn(zr[j], wr[j], s);
    float D = __fsub_rn(__fadd_rn(z2r, g_w2[k]), __fmul_rn(2.0f, s));
    return ((u64)__float_as_uint(D) << 32) | (u32)k;
}

__device__ __forceinline__ void load_tile(u32 sb, int t, int buf, int tid) {
    const char* bh = (const char*)g_whi;
    size_t gbase = (size_t)t * 64 * 128;     // 64 codes * 128B
    #pragma unroll
    for (int q = 0; q < 2; q++) {
        int i = tid + CTA * q;               // 512 chunks of 16B
        cp16(sb + OFF_B(buf) + SWZ((u32)(i * 16)), bh + gbase + (size_t)i * 16);
    }
    if (tid < 16)
        cp16(sb + OFF_W2(buf) + tid * 16,
             (const char*)g_w2 + (size_t)t * 256 + tid * 16);
}

// ---------------------------------------------------------------------------
// main: single bf16 HMMA GEMM + top-3 tracking + exact rescore
// (R10 structure verbatim; lo-plane deleted; MARGIN 1.2e-4)
// ---------------------------------------------------------------------------
__global__ __launch_bounds__(CTA, 2)
void vq_main(const float* __restrict__ z, const float* __restrict__ W) {
    extern __shared__ char sm[];
    const u32 sb = smem_u32(sm);
    const int tid = threadIdx.x, wid = tid >> 5, lane = tid & 31;
    float* zsm = (float*)(sm + OFF_Z);
    float* z2s = (float*)(sm + OFF_Z2);

    // ---- z -> smem (coalesced) ----
    const float4* gz = (const float4*)(z + (size_t)blockIdx.x * ROWS_B * DIM);
    #pragma unroll
    for (int q = 0; q < 8; q++) {
        int i = tid + CTA * q;               // 2048 float4
        int r = i >> 4, c = i & 15;
        *(float4*)(zsm + r * ZP + c * 4) = gz[i];
    }
    load_tile(sb, 0, 0, tid);
    CP_COMMIT();
    __syncthreads();

    // ---- build A = bf16(z) (SW128) + z2 (sequential, proven) ----
    #pragma unroll
    for (int q = 0; q < 16; q++) {
        int i = tid + CTA * q;               // 4096 u32 slots
        int r = i >> 5, pr = i & 31;
        float a = zsm[r * ZP + 2 * pr], b = zsm[r * ZP + 2 * pr + 1];
        __nv_bfloat162 h2 = __halves2bfloat162(__float2bfloat16(a),
                                               __float2bfloat16(b));
        *(u32*)(sm + OFF_A + SWZ((u32)(r * 128 + pr * 4))) = *(u32*)&h2;
    }
    if (tid < ROWS_B) {
        float s = 0.0f;
        #pragma unroll 8
        for (int j = 0; j < DIM; j++) {
            float v = zsm[tid * ZP + j];
            s = __fmaf_rn(v, v, s);
        }
        z2s[tid] = s;
    }
    __syncthreads();

    // ---- A fragments (held in registers for all tiles) ----
    u32 ahi[4][4];
    {
        int mat = lane >> 3, rl = lane & 7;
        u32 abase = (u32)((wid * 16 + (mat & 1) * 8 + rl) * 128 + (mat >> 1) * 16);
        #pragma unroll
        for (int kc = 0; kc < 4; kc++) {
            u32 sw = SWZ(abase + kc * 32);
            ldsm4(ahi[kc][0], ahi[kc][1], ahi[kc][2], ahi[kc][3], sb + OFF_A + sw);
        }
    }

    const int tg = lane & 3, rq = lane >> 2;
    float s1[2], s2[2], s3[2];
    int k1[2], k2[2];
    #pragma unroll
    for (int p = 0; p < 2; p++) {
        s1[p] = s2[p] = s3[p] = __int_as_float(0x7f800000);
        k1[p] = k2[p] = 0;
    }

    const int brl = lane & 7;
    const u32 bkoff = (u32)(((lane >> 4) * 32) + (((lane >> 3) & 1) * 16));

    for (int t = 0; t < NTILES; t++) {
        int buf = t & 1;
        CP_WAIT0();
        __syncthreads();
        if (t + 1 < NTILES) { load_tile(sb, t + 1, (t + 1) & 1, tid); CP_COMMIT(); }

        const u32 bhB = sb + OFF_B(buf);
        const float* w2b = (const float*)(sm + OFF_W2(buf));

        float d[8][4];
        #pragma unroll
        for (int n = 0; n < 8; n++)
            #pragma unroll
            for (int c = 0; c < 4; c++) d[n][c] = 0.0f;

        #pragma unroll
        for (int g = 0; g < 2; g++) {
            #pragma unroll
            for (int kp = 0; kp < 2; kp++) {
                u32 bh[4][4];
                #pragma unroll
                for (int i = 0; i < 4; i++) {
                    u32 off = SWZ((u32)(((g * 4 + i) * 8 + brl) * 128)
                                  + (u32)(2 * kp * 32) + bkoff);
                    ldsm4(bh[i][0], bh[i][1], bh[i][2], bh[i][3], bhB + off);
                }
                // round-robin over 4 independent accumulators
                #pragma unroll
                for (int i = 0; i < 4; i++) MMA(d[g*4+i], ahi[2*kp],   bh[i][0], bh[i][1]);
                #pragma unroll
                for (int i = 0; i < 4; i++) MMA(d[g*4+i], ahi[2*kp+1], bh[i][2], bh[i][3]);
            }
        }

        // ---- extract + top-3 tracking (R4/R10-proven) ----
        #pragma unroll
        for (int nc = 0; nc < 8; nc++) {
            float2 wv = *(const float2*)(w2b + nc * 8 + 2 * tg);
            int kb = t * 64 + nc * 8 + 2 * tg;
            float Dv[4] = { __fadd_rn(wv.x, d[nc][0]), __fadd_rn(wv.y, d[nc][1]),
                            __fadd_rn(wv.x, d[nc][2]), __fadd_rn(wv.y, d[nc][3]) };
            int   kv[4] = { kb, kb + 1, kb, kb + 1 };
            #pragma unroll
            for (int q = 0; q < 4; q++) {
                int p = q >> 1;
                float D = Dv[q];
                if (D < s3[p]) {
                    if (D < s1[p]) { s3[p]=s2[p]; s2[p]=s1[p]; k2[p]=k1[p];
                                     s1[p]=D; k1[p]=kv[q]; }
                    else if (D < s2[p]) { s3[p]=s2[p]; s2[p]=D; k2[p]=kv[q]; }
                    else s3[p] = D;
                }
            }
        }
    }

    // ---- per-row combine + exact rescore ----
    int flag[2];
    #pragma unroll
    for (int p = 0; p < 2; p++) {
        int rowc = wid * 16 + p * 8 + rq;
        float g = s1[p];
        g = fminf(g, __shfl_xor_sync(0xffffffffu, g, 1));
        g = fminf(g, __shfl_xor_sync(0xffffffffu, g, 2));
        float thr = __fadd_rn(g, MARGIN);
        flag[p] = (s3[p] <= thr) ? 1 : 0;

        u64 key = ~0ull;
        if (s1[p] <= thr) { u64 v = rescore(k1[p], zsm + rowc * ZP, z2s[rowc], W);
                            if (v < key) key = v; }
        if (s2[p] <= thr) { u64 v = rescore(k2[p], zsm + rowc * ZP, z2s[rowc], W);
                            if (v < key) key = v; }
        u64 o = __shfl_xor_sync(0xffffffffu, key, 1); if (o < key) key = o;
        o = __shfl_xor_sync(0xffffffffu, key, 2); if (o < key) key = o;
        if (tg == 0)
            g_idx[blockIdx.x * ROWS_B + rowc] = (int)(key & 0xffffffffULL);
    }

    // ---- cooperative exact full-rescan for flagged rows (rare at 1.2e-4) ----
    __syncwarp();
    #pragma unroll
    for (int p = 0; p < 2; p++) {
        unsigned f = __ballot_sync(0xffffffffu, flag[p] != 0);
        for (int r = 0; r < 8; r++) {
            if ((f >> (4 * r)) & 0xF) {
                int rowc = wid * 16 + p * 8 + r;
                const float* zr = zsm + rowc * ZP;
                float z2r = z2s[rowc];
                u64 bk = ~0ull;
                for (int k = lane; k < KC; k += 32) {
                    u64 v = rescore(k, zr, z2r, W);
                    if (v < bk) bk = v;
                }
                #pragma unroll
                for (int o = 16; o; o >>= 1) {
                    u64 v = __shfl_xor_sync(0xffffffffu, bk, o);
                    if (v < bk) bk = v;
                }
                if (lane == 0)
                    g_idx[blockIdx.x * ROWS_B + rowc] = (int)(bk & 0xffffffffULL);
            }
        }
    }
}

// ---------------------------------------------------------------------------
// output: gather + STE + loss partials  (proven)
// ---------------------------------------------------------------------------
__global__ __launch_bounds__(256)
void vq_out(const float* __restrict__ z, const float* __restrict__ W,
            float* __restrict__ out, int off) {
    __shared__ float red[256];
    int e0 = (blockIdx.x * 256 + threadIdx.x) * 4;
    int idx = g_idx[e0 >> 6];
    float4 zv = *(const float4*)(z + e0);
    float4 wv = *(const float4*)(W + (size_t)idx * DIM + (e0 & 63));
    float zz[4] = {zv.x, zv.y, zv.z, zv.w};
    float ww[4] = {wv.x, wv.y, wv.z, wv.w};
    float lsum = 0.0f;
    #pragma unroll
    for (int q = 0; q < 4; q++) {
        float dd = __fsub_rn(zz[q], ww[q]);
        lsum = __fmaf_rn(dd, dd, lsum);
        out[off + e0 + q] = __fadd_rn(zz[q], __fsub_rn(ww[q], zz[q]));
    }
    red[threadIdx.x] = lsum;
    __syncthreads();
    for (int s = 128; s > 0; s >>= 1) {
        if (threadIdx.x < s)
            red[threadIdx.x] = __fadd_rn(red[threadIdx.x], red[threadIdx.x + s]);
        __syncthreads();
    }
    if (threadIdx.x == 0) g_part[blockIdx.x] = red[0];
}

__global__ void loss_kernel(float* __restrict__ out) {
    __shared__ float red[256];
    float s = 0.0f;
    for (int i = threadIdx.x; i < 4096; i += 256) s = __fadd_rn(s, g_part[i]);
    red[threadIdx.x] = s;
    __syncthreads();
    for (int st = 128; st > 0; st >>= 1) {
        if (threadIdx.x < st)
            red[threadIdx.x] = __fadd_rn(red[threadIdx.x], red[threadIdx.x + st]);
        __syncthreads();
    }
    if (threadIdx.x == 0)
        out[0] = __fmul_rn(0.25f, __fdiv_rn(red[0], 4194304.0f));
}

// ---------------------------------------------------------------------------
extern "C" void kernel_launch(void* const* d_in, const int* in_sizes, int n_in,
                              void* d_out, int out_size) {
    const float* z = (const float*)d_in[0];
    const float* W = (const float*)d_in[1];
    if (n_in >= 2 && in_sizes[0] < in_sizes[1]) {
        const float* t = z; z = W; W = t;
    }
    float* out = (float*)d_out;
    const int off = (out_size > NROWS * DIM) ? 1 : 0;

    cudaFuncSetAttribute(vq_main, cudaFuncAttributeMaxDynamicSharedMemorySize,
                         SMEM_BYTES);
    prep_kernel<<<16, 256>>>(W);
    vq_main<<<NBLK, CTA, SMEM_BYTES>>>(z, W);
    vq_out<<<4096, 256>>>(z, W, out, off);
    if (off) loss_kernel<<<1, 256>>>(out);
}

// round 12
// speedup vs baseline: 1.8024x; 1.8024x over previous
#include <cuda_runtime.h>
#include <cuda_bf16.h>

typedef unsigned long long u64;
typedef unsigned int u32;

#define NROWS  65536
#define KC     4096
#define DIM    64
#define ROWS_B 128
#define NTILES 64          // B tiles of 64 codes
#define NBLK   512
#define CTA    256
#define MARGIN 1e-5f
#define ZP     68          // zsm pitch (floats)

// dynamic smem layout (bytes)
#define OFF_Z   0                         // 128*68*4 = 34816
#define OFF_Z2  34816                     // 128 floats
#define OFF_AHI 35328                     // 16384 (128B aligned)
#define OFF_ALO 51712                     // 16384
#define OFF_B(buf,m) (68096 + (buf)*16384 + (m)*8192)   // m: 0=hi 1=lo
#define OFF_W2(buf)  (100864 + (buf)*256)
#define OFF_BIDX 101376                   // 128 ints
#define OFF_RED  101888                   // 256 floats
#define SMEM_BYTES 102912

#define SWZ(x) ((x) ^ (((x) >> 3) & 0x70))

__device__ __nv_bfloat16 g_whi[KC * DIM];
__device__ __nv_bfloat16 g_wlo[KC * DIM];
__device__ float g_w2[KC];
__device__ float g_part[NBLK];
__device__ int   g_cnt;

// ---------------------------------------------------------------------------
__device__ __forceinline__ u32 smem_u32(const void* p) {
    u32 a;
    asm("{ .reg .u64 t; cvta.to.shared.u64 t, %1; cvt.u32.u64 %0, t; }"
        : "=r"(a) : "l"(p));
    return a;
}
__device__ __forceinline__ void cp16(u32 dst, const void* src) {
    asm volatile("cp.async.cg.shared.global [%0], [%1], 16;"
                 :: "r"(dst), "l"(src));
}
#define CP_COMMIT() asm volatile("cp.async.commit_group;" ::: "memory")
#define CP_WAIT0()  asm volatile("cp.async.wait_group 0;" ::: "memory")

__device__ __forceinline__ void ldsm4(u32& r0, u32& r1, u32& r2, u32& r3, u32 a) {
    asm volatile("ldmatrix.sync.aligned.m8n8.x4.shared.b16 {%0,%1,%2,%3}, [%4];"
                 : "=r"(r0), "=r"(r1), "=r"(r2), "=r"(r3) : "r"(a));
}
#define MMA(d, a, b0, b1)                                                     \
    asm volatile("mma.sync.aligned.m16n8k16.row.col.f32.bf16.bf16.f32 "       \
        "{%0,%1,%2,%3},{%4,%5,%6,%7},{%8,%9},{%0,%1,%2,%3};"                  \
        : "+f"((d)[0]), "+f"((d)[1]), "+f"((d)[2]), "+f"((d)[3])              \
        : "r"((a)[0]), "r"((a)[1]), "r"((a)[2]), "r"((a)[3]), "r"(b0), "r"(b1))

// ---------------------------------------------------------------------------
// prep: exact w2 (sequential, proven order) + bf16 hi/lo split of -2W
// ---------------------------------------------------------------------------
__global__ void prep_kernel(const float* __restrict__ W) {
    int k = blockIdx.x * 256 + threadIdx.x;      // grid 16 x 256
    float s = 0.0f;
    #pragma unroll 8
    for (int j = 0; j < DIM; j++) {
        float wv = W[k * DIM + j];
        s = __fmaf_rn(wv, wv, s);
        float wp = -2.0f * wv;               // exact scale
        __nv_bfloat16 h = __float2bfloat16(wp);
        float r = __fsub_rn(wp, __bfloat162float(h));
        g_whi[k * DIM + j] = h;
        g_wlo[k * DIM + j] = __float2bfloat16(r);
    }
    g_w2[k] = s;
}

// ---------------------------------------------------------------------------
__device__ __forceinline__ u64 rescore(int k, const float* zr, float z2r,
                                       const float* __restrict__ W) {
    const float* wr = W + (size_t)k * DIM;
    float s = 0.0f;
    #pragma unroll 8
    for (int j = 0; j < DIM; j++) s = __fmaf_rn(zr[j], wr[j], s);
    float D = __fsub_rn(__fadd_rn(z2r, g_w2[k]), __fmul_rn(2.0f, s));
    return ((u64)__float_as_uint(D) << 32) | (u32)k;
}

__device__ __forceinline__ void load_tile(u32 sb, int t, int buf, int tid) {
    const char* bh = (const char*)g_whi;
    const char* bl = (const char*)g_wlo;
    size_t gbase = (size_t)t * 64 * 128;     // 64 codes * 128B
    #pragma unroll
    for (int q = 0; q < 2; q++) {
        int i = tid + CTA * q;               // 512 chunks of 16B
        u32 sw = SWZ((u32)(i * 16));
        cp16(sb + OFF_B(buf, 0) + sw, bh + gbase + (size_t)i * 16);
        cp16(sb + OFF_B(buf, 1) + sw, bl + gbase + (size_t)i * 16);
    }
    if (tid < 16)
        cp16(sb + OFF_W2(buf) + tid * 16,
             (const char*)g_w2 + (size_t)t * 256 + tid * 16);
}

// ---------------------------------------------------------------------------
// main: split-bf16 HMMA distances + top-3 tracking + exact rescore
// (mainloop byte-identical to the measured 563.7/598.1us kernel)
// + fused epilogue: gather + STE + loss (R5/R6-proven)
// ---------------------------------------------------------------------------
__global__ __launch_bounds__(CTA, 2)
void vq_main(const float* __restrict__ z, const float* __restrict__ W,
             float* __restrict__ out, int off) {
    extern __shared__ char sm[];
    const u32 sb = smem_u32(sm);
    const int tid = threadIdx.x, wid = tid >> 5, lane = tid & 31;
    float* zsm = (float*)(sm + OFF_Z);
    float* z2s = (float*)(sm + OFF_Z2);
    int* bidx = (int*)(sm + OFF_BIDX);

    // ---- z -> smem (coalesced) ----
    const float4* gz = (const float4*)(z + (size_t)blockIdx.x * ROWS_B * DIM);
    #pragma unroll
    for (int q = 0; q < 8; q++) {
        int i = tid + CTA * q;               // 2048 float4
        int r = i >> 4, c = i & 15;
        *(float4*)(zsm + r * ZP + c * 4) = gz[i];
    }
    load_tile(sb, 0, 0, tid);
    CP_COMMIT();
    __syncthreads();

    // ---- build A_hi/A_lo (swizzled bf16x2) + z2 ----
    #pragma unroll
    for (int q = 0; q < 16; q++) {
        int i = tid + CTA * q;               // 4096 u32 slots
        int r = i >> 5, pr = i & 31;
        float a = zsm[r * ZP + 2 * pr], b = zsm[r * ZP + 2 * pr + 1];
        __nv_bfloat16 ha = __float2bfloat16(a), hb = __float2bfloat16(b);
        __nv_bfloat162 h2 = __halves2bfloat162(ha, hb);
        float ra = __fsub_rn(a, __bfloat162float(ha));
        float rb = __fsub_rn(b, __bfloat162float(hb));
        __nv_bfloat162 l2 = __halves2bfloat162(__float2bfloat16(ra),
                                               __float2bfloat16(rb));
        u32 sw = SWZ((u32)(r * 128 + pr * 4));
        *(u32*)(sm + OFF_AHI + sw) = *(u32*)&h2;
        *(u32*)(sm + OFF_ALO + sw) = *(u32*)&l2;
    }
    if (tid < ROWS_B) {
        float s = 0.0f;
        #pragma unroll 8
        for (int j = 0; j < DIM; j++) {
            float v = zsm[tid * ZP + j];
            s = __fmaf_rn(v, v, s);
        }
        z2s[tid] = s;
    }
    __syncthreads();

    // ---- A fragments (held in registers for all tiles) ----
    u32 ahi[4][4], alo[4][4];
    {
        int mat = lane >> 3, rl = lane & 7;
        u32 abase = (u32)((wid * 16 + (mat & 1) * 8 + rl) * 128 + (mat >> 1) * 16);
        #pragma unroll
        for (int kc = 0; kc < 4; kc++) {
            u32 sw = SWZ(abase + kc * 32);
            ldsm4(ahi[kc][0], ahi[kc][1], ahi[kc][2], ahi[kc][3], sb + OFF_AHI + sw);
            ldsm4(alo[kc][0], alo[kc][1], alo[kc][2], alo[kc][3], sb + OFF_ALO + sw);
        }
    }

    const int tg = lane & 3, rq = lane >> 2;
    float s1[2], s2[2], s3[2];
    int k1[2], k2[2];
    #pragma unroll
    for (int p = 0; p < 2; p++) {
        s1[p] = s2[p] = s3[p] = __int_as_float(0x7f800000);
        k1[p] = k2[p] = 0;
    }

    const int brl = lane & 7;
    const u32 bkoff = (u32)(((lane >> 4) * 32) + (((lane >> 3) & 1) * 16));

    for (int t = 0; t < NTILES; t++) {
        int buf = t & 1;
        CP_WAIT0();
        __syncthreads();
        if (t + 1 < NTILES) { load_tile(sb, t + 1, (t + 1) & 1, tid); CP_COMMIT(); }

        const u32 bhB = sb + OFF_B(buf, 0);
        const u32 blB = sb + OFF_B(buf, 1);
        const float* w2b = (const float*)(sm + OFF_W2(buf));

        float d[8][4];
        #pragma unroll
        for (int n = 0; n < 8; n++)
            #pragma unroll
            for (int c = 0; c < 4; c++) d[n][c] = 0.0f;

        #pragma unroll
        for (int g = 0; g < 2; g++) {
            #pragma unroll
            for (int kp = 0; kp < 2; kp++) {
                u32 bh[4][4], bl[4][4];
                #pragma unroll
                for (int i = 0; i < 4; i++) {
                    u32 off2 = SWZ((u32)(((g * 4 + i) * 8 + brl) * 128)
                                   + (u32)(2 * kp * 32) + bkoff);
                    ldsm4(bh[i][0], bh[i][1], bh[i][2], bh[i][3], bhB + off2);
                    ldsm4(bl[i][0], bl[i][1], bl[i][2], bl[i][3], blB + off2);
                }
                // round-robin over 4 independent accumulators (hides HMMA latency)
                #pragma unroll
                for (int i = 0; i < 4; i++) MMA(d[g*4+i], ahi[2*kp],   bh[i][0], bh[i][1]);
                #pragma unroll
                for (int i = 0; i < 4; i++) MMA(d[g*4+i], ahi[2*kp+1], bh[i][2], bh[i][3]);
                #pragma unroll
                for (int i = 0; i < 4; i++) MMA(d[g*4+i], alo[2*kp],   bh[i][0], bh[i][1]);
                #pragma unroll
                for (int i = 0; i < 4; i++) MMA(d[g*4+i], alo[2*kp+1], bh[i][2], bh[i][3]);
                #pragma unroll
                for (int i = 0; i < 4; i++) MMA(d[g*4+i], ahi[2*kp],   bl[i][0], bl[i][1]);
                #pragma unroll
                for (int i = 0; i < 4; i++) MMA(d[g*4+i], ahi[2*kp+1], bl[i][2], bl[i][3]);
            }
        }

        // ---- extract + top-3 tracking ----
        #pragma unroll
        for (int nc = 0; nc < 8; nc++) {
            float2 wv = *(const float2*)(w2b + nc * 8 + 2 * tg);
            int kb = t * 64 + nc * 8 + 2 * tg;
            float Dv[4] = { __fadd_rn(wv.x, d[nc][0]), __fadd_rn(wv.y, d[nc][1]),
                            __fadd_rn(wv.x, d[nc][2]), __fadd_rn(wv.y, d[nc][3]) };
            int   kv[4] = { kb, kb + 1, kb, kb + 1 };
            #pragma unroll
            for (int q = 0; q < 4; q++) {
                int p = q >> 1;
                float D = Dv[q];
                if (D < s3[p]) {
                    if (D < s1[p]) { s3[p]=s2[p]; s2[p]=s1[p]; k2[p]=k1[p];
                                     s1[p]=D; k1[p]=kv[q]; }
                    else if (D < s2[p]) { s3[p]=s2[p]; s2[p]=D; k2[p]=kv[q]; }
                    else s3[p] = D;
                }
            }
        }
    }

    // ---- per-row combine + exact rescore ----
    int flag[2];
    #pragma unroll
    for (int p = 0; p < 2; p++) {
        int rowc = wid * 16 + p * 8 + rq;
        float g = s1[p];
        g = fminf(g, __shfl_xor_sync(0xffffffffu, g, 1));
        g = fminf(g, __shfl_xor_sync(0xffffffffu, g, 2));
        float thr = __fadd_rn(g, MARGIN);
        flag[p] = (s3[p] <= thr) ? 1 : 0;

        u64 key = ~0ull;
        if (s1[p] <= thr) { u64 v = rescore(k1[p], zsm + rowc * ZP, z2s[rowc], W);
                            if (v < key) key = v; }
        if (s2[p] <= thr) { u64 v = rescore(k2[p], zsm + rowc * ZP, z2s[rowc], W);
                            if (v < key) key = v; }
        u64 o = __shfl_xor_sync(0xffffffffu, key, 1); if (o < key) key = o;
        o = __shfl_xor_sync(0xffffffffu, key, 2); if (o < key) key = o;
        if (tg == 0) bidx[rowc] = (int)(key & 0xffffffffULL);
    }

    // ---- cooperative exact full-rescan for flagged rows (rare at 1e-5) ----
    __syncwarp();
    #pragma unroll
    for (int p = 0; p < 2; p++) {
        unsigned f = __ballot_sync(0xffffffffu, flag[p] != 0);
        for (int r = 0; r < 8; r++) {
            if ((f >> (4 * r)) & 0xF) {
                int rowc = wid * 16 + p * 8 + r;
                const float* zr = zsm + rowc * ZP;
                float z2r = z2s[rowc];
                u64 bk = ~0ull;
                for (int k = lane; k < KC; k += 32) {
                    u64 v = rescore(k, zr, z2r, W);
                    if (v < bk) bk = v;
                }
                #pragma unroll
                for (int o = 16; o; o >>= 1) {
                    u64 v = __shfl_xor_sync(0xffffffffu, bk, o);
                    if (v < bk) bk = v;
                }
                if (lane == 0) bidx[rowc] = (int)(bk & 0xffffffffULL);
            }
        }
    }
    __syncthreads();

    // ---- fused epilogue: gather + STE + loss partial (R5/R6-proven) ----
    float lsum = 0.0f;
    const size_t obase = (size_t)blockIdx.x * ROWS_B * DIM + off;
    #pragma unroll
    for (int q = 0; q < 8; q++) {
        int i = tid + CTA * q;               // 2048 float4 slots
        int row = i >> 4, c4 = i & 15;
        float4 zv = *(const float4*)(zsm + row * ZP + c4 * 4);   // resident z
        float4 wv = *(const float4*)(W + (size_t)bidx[row] * DIM + c4 * 4);
        float zz[4] = {zv.x, zv.y, zv.z, zv.w};
        float ww[4] = {wv.x, wv.y, wv.z, wv.w};
        #pragma unroll
        for (int c = 0; c < 4; c++) {
            float dd = __fsub_rn(zz[c], ww[c]);
            lsum = __fmaf_rn(dd, dd, lsum);
            out[obase + i * 4 + c] = __fadd_rn(zz[c], __fsub_rn(ww[c], zz[c]));
        }
    }

    float* red = (float*)(sm + OFF_RED);
    red[tid] = lsum;
    __syncthreads();
    for (int s = CTA / 2; s > 0; s >>= 1) {
        if (tid < s) red[tid] = __fadd_rn(red[tid], red[tid + s]);
        __syncthreads();
    }
    __shared__ int lastf;
    if (tid == 0) {
        g_part[blockIdx.x] = red[0];
        __threadfence();
        lastf = (atomicAdd(&g_cnt, 1) == NBLK - 1) ? 1 : 0;
    }
    __syncthreads();

    // ---- last CTA: deterministic final loss reduction (R5-proven) ----
    if (lastf) {
        __threadfence();
        float s = __fadd_rn(g_part[tid], g_part[tid + 256]);
        red[tid] = s;
        __syncthreads();
        for (int st = CTA / 2; st > 0; st >>= 1) {
            if (tid < st) red[tid] = __fadd_rn(red[tid], red[tid + st]);
            __syncthreads();
        }
        if (tid == 0) {
            if (off) out[0] = __fmul_rn(0.25f, __fdiv_rn(red[0], 4194304.0f));
            g_cnt = 0;   // reset for next graph replay
        }
    }
}

// ---------------------------------------------------------------------------
extern "C" void kernel_launch(void* const* d_in, const int* in_sizes, int n_in,
                              void* d_out, int out_size) {
    const float* z = (const float*)d_in[0];
    const float* W = (const float*)d_in[1];
    if (n_in >= 2 && in_sizes[0] < in_sizes[1]) {
        const float* t = z; z = W; W = t;
    }
    float* out = (float*)d_out;
    const int off = (out_size > NROWS * DIM) ? 1 : 0;

    cudaFuncSetAttribute(vq_main, cudaFuncAttributeMaxDynamicSharedMemorySize,
                         SMEM_BYTES);
    prep_kernel<<<16, 256>>>(W);
    vq_main<<<NBLK, CTA, SMEM_BYTES>>>(z, W, out, off);
}